// round 7
// baseline (speedup 1.0000x reference)
#include <cuda_runtime.h>
#include <cuda_bf16.h>

#define N_PRED 2048
#define T_RUNS 16
#define M_BOX  2048
#define EPS_F  1e-7f

#define GB      16
#define NBINS   (GB*GB)
#define BIN_ORG (-28.0f)
#define BIN_INV (1.0f/42.0f)
#define WH_MAX  55.0f          // box w,h in [5,55)
#define CAP     1280           // smem slab capacity (5 rows avg ~640)

// ---- device scratch (no allocations allowed) ----
__device__ float4 g_sbox[T_RUNS][M_BOX];      // binned boxes (x1,y1,x2,y2)
__device__ int    g_bstart[T_RUNS][NBINS+1];  // box bin prefix offsets per run
__device__ float4 g_pbox[N_PRED];             // pred boxes, bin-sorted
__device__ int    g_perm[N_PRED];             // sorted slot -> original pred idx
__device__ int    g_pstart[NBINS+1];          // pred bin prefix offsets

__device__ __forceinline__ int bin1d(float v) {
    int b = (int)floorf((v - BIN_ORG) * BIN_INV);
    return min(max(b, 0), GB - 1);
}

// ---------------------------------------------------------------------------
// prep: blocks 0..15 counting-sort run t's boxes; block 16 sorts preds,
// writes g_pstart, zeroes out. 1024 threads x 2 boxes; boxes are 8B-aligned
// (24B stride) so each box is 3 independent float2 loads (R4's scalar gather
// was the prep bottleneck).
// ---------------------------------------------------------------------------
__global__ __launch_bounds__(1024)
void prep_kernel(const float* __restrict__ pred,
                 const float* __restrict__ dropout_preds,
                 float* __restrict__ out)
{
    __shared__ int cnt[NBINS];
    __shared__ int wsum[8];
    const int tid  = threadIdx.x;
    const int lane = tid & 31, wid = tid >> 5;
    const bool is_box_block = (blockIdx.x < T_RUNS);

    if (tid < NBINS) cnt[tid] = 0;
    if (!is_box_block) {               // out is poisoned; zero before match
        out[tid] = 0.0f;
        out[tid + 1024] = 0.0f;
    }
    __syncthreads();

    const float* src = is_box_block
        ? dropout_preds + (size_t)blockIdx.x * M_BOX * 6
        : pred;

    // ---- count (2 boxes per thread, float2 loads) ----
    float4 box[2];
    int    bin[2];
    #pragma unroll
    for (int k = 0; k < 2; ++k) {
        const int i = tid + k * 1024;
        const float2* b2 = reinterpret_cast<const float2*>(src + i * 6);
        float2 p0 = b2[0];             // x1, y1
        float2 p1 = b2[1];             // x2, y2
        box[k] = make_float4(p0.x, p0.y, p1.x, p1.y);
        bin[k] = bin1d(p0.y) * GB + bin1d(p0.x);
        atomicAdd(&cnt[bin[k]], 1);
    }
    __syncthreads();

    // ---- exclusive scan over 256 bins (threads 0..255) ----
    int start = 0;
    if (tid < NBINS) {
        int v = cnt[tid];
        int inc = v;
        #pragma unroll
        for (int o = 1; o < 32; o <<= 1) {
            int n = __shfl_up_sync(0xffffffffu, inc, o);
            if (lane >= o) inc += n;
        }
        if (lane == 31) wsum[wid] = inc;
        start = inc - v;
    }
    __syncthreads();
    if (wid == 0) {
        int w = (lane < 8) ? wsum[lane] : 0;
        int wi = w;
        #pragma unroll
        for (int o = 1; o < 8; o <<= 1) {
            int n = __shfl_up_sync(0xffffffffu, wi, o);
            if (lane >= o) wi += n;
        }
        if (lane < 8) wsum[lane] = wi - w;   // exclusive warp offsets
    }
    __syncthreads();
    if (tid < NBINS) {
        start += wsum[wid];
        cnt[tid] = start;                    // running scatter offsets
    }
    __syncthreads();

    // ---- scatter ----
    if (is_box_block) {
        const int t = blockIdx.x;
        if (tid < NBINS) g_bstart[t][tid] = start;
        if (tid == 0)    g_bstart[t][NBINS] = M_BOX;
        #pragma unroll
        for (int k = 0; k < 2; ++k) {
            int pos = atomicAdd(&cnt[bin[k]], 1);
            g_sbox[t][pos] = box[k];
        }
    } else {
        if (tid < NBINS) g_pstart[tid] = start;
        if (tid == 0)    g_pstart[NBINS] = N_PRED;
        #pragma unroll
        for (int k = 0; k < 2; ++k) {
            int pos = atomicAdd(&cnt[bin[k]], 1);
            g_pbox[pos] = box[k];
            g_perm[pos] = tid + k * 1024;
        }
    }
}

// ---------------------------------------------------------------------------
// match: CTA = (pred-y-row yr, run t), 512 threads = 16 warps. Slab for rows
// [yr-2, yr+2] filled once into smem. ONE WARP PER PRED: 32 lanes scan 32
// consecutive boxes per step (coalesced LDS, lane-level MLP), warp-uniform
// early exit via __any_sync after each 32-chunk. A pred's per-row window is
// ~25-35 boxes, so usually a single lane-parallel step per y-row.
// ---------------------------------------------------------------------------
__global__ __launch_bounds__(512)
void match_kernel(float* __restrict__ out)
{
    __shared__ float4 sbox[CAP];
    __shared__ float  snarea[CAP];
    __shared__ int    sbs[5 * GB + 1];

    const int tid  = threadIdx.x;
    const int lane = tid & 31, wid = tid >> 5;
    const int yr   = blockIdx.x;
    const int t    = blockIdx.y;

    const int r0 = max(yr - 2, 0), r1 = min(yr + 2, GB - 1);
    const int bin_lo = r0 * GB, bin_hi = (r1 + 1) * GB;
    const int nbs = bin_hi - bin_lo + 1;      // <= 81

    const int base = __ldg(&g_bstart[t][bin_lo]);
    const int endi = __ldg(&g_bstart[t][bin_hi]);
    const int n    = endi - base;

    if (tid < nbs) sbs[tid] = g_bstart[t][bin_lo + tid];
    const int ncap = min(n, CAP);
    for (int i = tid; i < ncap; i += 512) {
        float4 b  = g_sbox[t][base + i];
        sbox[i]   = b;
        snarea[i] = -((b.z - b.x) * (b.w - b.y));
    }
    __syncthreads();

    const int ps = g_pstart[yr * GB], pe = g_pstart[(yr + 1) * GB];
    const bool all_smem = (n <= CAP);         // always true for uniform data

    for (int slot = ps + wid; slot < pe; slot += 16) {
        const float4 a  = g_pbox[slot];       // warp-broadcast LDG
        const float thr = (a.z - a.x) * (a.w - a.y) + EPS_F;

        const int xb0 = bin1d(a.x - WH_MAX), xb1 = bin1d(a.z);
        const int yb0 = max(bin1d(a.y - WH_MAX), r0);
        const int yb1 = min(bin1d(a.w), r1);

        bool found = false;
        if (all_smem) {
            for (int yb = yb0; yb <= yb1 && !found; ++yb) {
                const int rb = yb * GB - bin_lo;
                const int s  = sbs[rb + xb0] - base;
                const int e  = sbs[rb + xb1 + 1] - base;
                for (int m0 = s; m0 < e; m0 += 32) {
                    const int m = m0 + lane;
                    bool hit = false;
                    if (m < e) {
                        float4 b  = sbox[m];  // coalesced LDS.128 across lanes
                        float ix1 = fmaxf(a.x, b.x);
                        float iy1 = fmaxf(a.y, b.y);
                        float ix2 = fminf(a.z, b.z);
                        float iy2 = fminf(a.w, b.w);
                        float dx  = fmaxf(ix2 - ix1, 0.0f);
                        float dy  = iy2 - iy1;   // dy<0 => inter<=0 < thr
                        hit = fmaf(3.0f, dx * dy, snarea[m]) > thr;
                    }
                    if (__any_sync(0xffffffffu, hit)) { found = true; break; }
                }
            }
        } else {                                    // safety fallback (gmem)
            for (int yb = yb0; yb <= yb1 && !found; ++yb) {
                const int rb = yb * GB - bin_lo;
                const int s  = sbs[rb + xb0];
                const int e  = sbs[rb + xb1 + 1];
                for (int m0 = s; m0 < e; m0 += 32) {
                    const int m = m0 + lane;
                    bool hit = false;
                    if (m < e) {
                        float4 b  = g_sbox[t][m];
                        float na  = -((b.z - b.x) * (b.w - b.y));
                        float ix1 = fmaxf(a.x, b.x);
                        float iy1 = fmaxf(a.y, b.y);
                        float ix2 = fminf(a.z, b.z);
                        float iy2 = fminf(a.w, b.w);
                        float dx  = fmaxf(ix2 - ix1, 0.0f);
                        float dy  = iy2 - iy1;
                        hit = fmaf(3.0f, dx * dy, na) > thr;
                    }
                    if (__any_sync(0xffffffffu, hit)) { found = true; break; }
                }
            }
        }

        // 16 adds of exactly 1/16: order-independent & exact -> deterministic
        if (found && lane == 0)
            atomicAdd(&out[g_perm[slot]], 1.0f / (float)T_RUNS);
    }
}

extern "C" void kernel_launch(void* const* d_in, const int* in_sizes, int n_in,
                              void* d_out, int out_size)
{
    const float* pred          = (const float*)d_in[0]; // [2048, 6]
    const float* dropout_preds = (const float*)d_in[1]; // [16, 2048, 6]
    // d_in[2] (dropout_cls_confs) unused by the reference computation.
    float* out = (float*)d_out;                          // [2048]

    prep_kernel<<<T_RUNS + 1, 1024>>>(pred, dropout_preds, out);
    match_kernel<<<dim3(GB, T_RUNS), 512>>>(out);
}

// round 8
// speedup vs baseline: 1.0202x; 1.0202x over previous
#include <cuda_runtime.h>
#include <cuda_bf16.h>

#define N_PRED 2048
#define T_RUNS 16
#define M_BOX  2048
#define EPS_F  1e-7f

#define GB      16
#define NBINS   (GB*GB)
#define BIN_ORG (-28.0f)
#define BIN_INV (1.0f/42.0f)
#define WH_MAX  55.0f          // box w,h in [5,55)
#define CAP     1280           // smem slab capacity (5 rows avg ~640)

// ---- device scratch (no allocations allowed) ----
__device__ float4 g_sbox[T_RUNS][M_BOX];      // binned boxes (x1,y1,x2,y2)
__device__ int    g_bstart[T_RUNS][NBINS+1];  // box bin prefix offsets per run
__device__ float4 g_pbox[N_PRED];             // pred boxes, bin-sorted
__device__ int    g_perm[N_PRED];             // sorted slot -> original pred idx
__device__ int    g_pstart[NBINS+1];          // pred bin prefix offsets

__device__ __forceinline__ int bin1d(float v) {
    int b = (int)floorf((v - BIN_ORG) * BIN_INV);
    return min(max(b, 0), GB - 1);
}

// ---------------------------------------------------------------------------
// prep (R2 shape — cheapest measured): blocks 0..15 counting-sort run t's
// boxes; block 16 sorts preds, writes g_pstart, zeroes out. 256 thr == NBINS.
// ---------------------------------------------------------------------------
__global__ __launch_bounds__(256)
void prep_kernel(const float* __restrict__ pred,
                 const float* __restrict__ dropout_preds,
                 float* __restrict__ out)
{
    __shared__ int cnt[NBINS];
    __shared__ int wsum[8];
    const int tid  = threadIdx.x;
    const int lane = tid & 31, wid = tid >> 5;
    const bool is_box_block = (blockIdx.x < T_RUNS);

    cnt[tid] = 0;
    __syncthreads();

    // ---- count ----
    float4 box[8];
    int    bin[8];
    if (is_box_block) {
        const float* src = dropout_preds + (size_t)blockIdx.x * M_BOX * 6;
        #pragma unroll
        for (int k = 0; k < M_BOX / 256; ++k) {
            const float* b6 = src + (tid + k * 256) * 6;
            box[k] = make_float4(b6[0], b6[1], b6[2], b6[3]);
            bin[k] = bin1d(box[k].y) * GB + bin1d(box[k].x);
            atomicAdd(&cnt[bin[k]], 1);
        }
    } else {
        #pragma unroll
        for (int k = 0; k < N_PRED / 256; ++k) {
            int p = tid + k * 256;
            const float* a = pred + p * 6;
            box[k] = make_float4(a[0], a[1], a[2], a[3]);
            bin[k] = bin1d(box[k].y) * GB + bin1d(box[k].x);
            atomicAdd(&cnt[bin[k]], 1);
            out[p] = 0.0f;        // out is poisoned; zero before match
        }
    }
    __syncthreads();

    // ---- exclusive scan over 256 bins (shfl + 8-way combine) ----
    int v = cnt[tid];
    int inc = v;
    #pragma unroll
    for (int o = 1; o < 32; o <<= 1) {
        int n = __shfl_up_sync(0xffffffffu, inc, o);
        if (lane >= o) inc += n;
    }
    if (lane == 31) wsum[wid] = inc;
    __syncthreads();
    if (wid == 0) {
        int w = (lane < 8) ? wsum[lane] : 0;
        int wi = w;
        #pragma unroll
        for (int o = 1; o < 8; o <<= 1) {
            int n = __shfl_up_sync(0xffffffffu, wi, o);
            if (lane >= o) wi += n;
        }
        if (lane < 8) wsum[lane] = wi - w;
    }
    __syncthreads();
    const int start = inc - v + wsum[wid];
    cnt[tid] = start;                       // running scatter offsets
    __syncthreads();

    // ---- scatter ----
    if (is_box_block) {
        const int t = blockIdx.x;
        g_bstart[t][tid] = start;
        if (tid == 0) g_bstart[t][NBINS] = M_BOX;
        #pragma unroll
        for (int k = 0; k < M_BOX / 256; ++k) {
            int pos = atomicAdd(&cnt[bin[k]], 1);
            g_sbox[t][pos] = box[k];
        }
    } else {
        g_pstart[tid] = start;
        if (tid == 0) g_pstart[NBINS] = N_PRED;
        #pragma unroll
        for (int k = 0; k < N_PRED / 256; ++k) {
            int pos = atomicAdd(&cnt[bin[k]], 1);
            g_pbox[pos] = box[k];
            g_perm[pos] = tid + k * 256;
        }
    }
}

#define IOU_STEP(BV, NA, ACC)                                    \
    {   float ix1 = fmaxf(a.x, (BV).x);                          \
        float iy1 = fmaxf(a.y, (BV).y);                          \
        float ix2 = fminf(a.z, (BV).z);                          \
        float iy2 = fminf(a.w, (BV).w);                          \
        float dx  = fmaxf(ix2 - ix1, 0.0f);                      \
        float dy  = iy2 - iy1;   /* dy<0 => inter<=0 < thr */    \
        ACC = fmaxf(ACC, fmaf(3.0f, dx * dy, (NA))); }

// ---------------------------------------------------------------------------
// match: CTA = (pred-y-row yr, run t), 128 threads, ONE THREAD PER PRED
// (R4's winning mapping), slab filled ONCE. The inner loop is a manual
// 4-wide software pipeline: 8 LDS issued per batch, then 4 independent IoU
// chains into 4 accumulators, so LDS latency is hidden by the batch's own
// issue stream instead of (absent) sibling warps. Early exit per y-row.
// ---------------------------------------------------------------------------
__global__ __launch_bounds__(128)
void match_kernel(float* __restrict__ out)
{
    __shared__ float4 sbox[CAP];
    __shared__ float  snarea[CAP];
    __shared__ int    sbs[5 * GB + 1];

    const int tid = threadIdx.x;
    const int yr  = blockIdx.x;
    const int t   = blockIdx.y;

    const int r0 = max(yr - 2, 0), r1 = min(yr + 2, GB - 1);
    const int bin_lo = r0 * GB, bin_hi = (r1 + 1) * GB;
    const int nbs = bin_hi - bin_lo + 1;      // <= 81

    const int base = __ldg(&g_bstart[t][bin_lo]);
    const int endi = __ldg(&g_bstart[t][bin_hi]);
    const int n    = endi - base;

    if (tid < nbs) sbs[tid] = g_bstart[t][bin_lo + tid];
    const int ncap = min(n, CAP);
    for (int i = tid; i < ncap; i += 128) {
        float4 b  = g_sbox[t][base + i];
        sbox[i]   = b;
        snarea[i] = -((b.z - b.x) * (b.w - b.y));
    }
    __syncthreads();

    const int ps = g_pstart[yr * GB], pe = g_pstart[(yr + 1) * GB];
    const bool all_smem = (n <= CAP);         // always true for uniform data

    for (int slot = ps + tid; slot < pe; slot += 128) {
        const float4 a  = g_pbox[slot];
        const float thr = (a.z - a.x) * (a.w - a.y) + EPS_F;

        const int xb0 = bin1d(a.x - WH_MAX), xb1 = bin1d(a.z);
        const int yb0 = max(bin1d(a.y - WH_MAX), r0);
        const int yb1 = min(bin1d(a.w), r1);

        float acc0 = -1e30f, acc1 = -1e30f, acc2 = -1e30f, acc3 = -1e30f;

        if (all_smem) {
            for (int yb = yb0; yb <= yb1; ++yb) {
                const int rb = yb * GB - bin_lo;
                const int s  = sbs[rb + xb0] - base;
                const int e  = sbs[rb + xb1 + 1] - base;
                int m = s;
                for (; m + 4 <= e; m += 4) {
                    // issue all 8 LDS up front, then 4 independent chains
                    float4 b0 = sbox[m],     b1 = sbox[m + 1];
                    float4 b2 = sbox[m + 2], b3 = sbox[m + 3];
                    float n0 = snarea[m],     n1 = snarea[m + 1];
                    float n2 = snarea[m + 2], n3 = snarea[m + 3];
                    IOU_STEP(b0, n0, acc0);
                    IOU_STEP(b1, n1, acc1);
                    IOU_STEP(b2, n2, acc2);
                    IOU_STEP(b3, n3, acc3);
                }
                for (; m < e; ++m) {
                    float4 b = sbox[m];
                    IOU_STEP(b, snarea[m], acc0);
                }
                if (fmaxf(fmaxf(acc0, acc1), fmaxf(acc2, acc3)) > thr) break;
            }
        } else {                                   // safety fallback (gmem)
            for (int yb = yb0; yb <= yb1; ++yb) {
                const int rb = yb * GB - bin_lo;
                const int s  = sbs[rb + xb0];
                const int e  = sbs[rb + xb1 + 1];
                for (int m = s; m < e; ++m) {
                    float4 b = g_sbox[t][m];
                    float na = -((b.z - b.x) * (b.w - b.y));
                    IOU_STEP(b, na, acc0);
                }
                if (acc0 > thr) break;
            }
        }

        const float best = fmaxf(fmaxf(acc0, acc1), fmaxf(acc2, acc3));
        // 16 adds of exactly 1/16: order-independent & exact -> deterministic
        if (best > thr) atomicAdd(&out[g_perm[slot]], 1.0f / (float)T_RUNS);
    }
}

extern "C" void kernel_launch(void* const* d_in, const int* in_sizes, int n_in,
                              void* d_out, int out_size)
{
    const float* pred          = (const float*)d_in[0]; // [2048, 6]
    const float* dropout_preds = (const float*)d_in[1]; // [16, 2048, 6]
    // d_in[2] (dropout_cls_confs) unused by the reference computation.
    float* out = (float*)d_out;                          // [2048]

    prep_kernel<<<T_RUNS + 1, 256>>>(pred, dropout_preds, out);
    match_kernel<<<dim3(GB, T_RUNS), 128>>>(out);
}

// round 9
// speedup vs baseline: 1.1064x; 1.0845x over previous
#include <cuda_runtime.h>
#include <cuda_bf16.h>

#define N_PRED 2048
#define T_RUNS 16
#define M_BOX  2048
#define EPS_F  1e-7f

#define GB      16
#define NBINS   (GB*GB)
#define BIN_ORG (-28.0f)
#define BIN_INV (1.0f/42.0f)
#define WH_MAX  55.0f          // box w,h in [5,55)
#define CAP     1280           // smem slab capacity (5 rows avg ~640)
#define NCTA    256

// ---- device scratch (no allocations allowed) ----
__device__ float4 g_sbox[T_RUNS][M_BOX];      // binned boxes (x1,y1,x2,y2)
__device__ int    g_bstart[T_RUNS][NBINS+1];  // box bin prefix offsets per run
__device__ float4 g_pbox[N_PRED];             // pred boxes, bin-sorted
__device__ int    g_perm[N_PRED];             // sorted slot -> original pred idx
__device__ int    g_pstart[NBINS+1];          // pred bin prefix offsets
__device__ volatile int g_sync = 0;           // prep-done counter (reset each run)
__device__ int    g_done = 0;                 // match-done counter (reset each run)

__device__ __forceinline__ int bin1d(float v) {
    int b = (int)floorf((v - BIN_ORG) * BIN_INV);
    return min(max(b, 0), GB - 1);
}

// ---------------------------------------------------------------------------
// Fused kernel: CTAs 0..15 counting-sort run t's boxes, CTA 16 sorts preds +
// zeroes out; everyone spins on an L2 counter, then all 256 CTAs run the
// match phase (CTA = (t<<4)|yr). All 256 CTAs are co-resident (8/SM cap), so
// the spin cannot deadlock. Last CTA resets counters -> replay-safe.
// ---------------------------------------------------------------------------
__global__ __launch_bounds__(256)
void fused_kernel(const float* __restrict__ pred,
                  const float* __restrict__ dropout_preds,
                  float* __restrict__ out)
{
    __shared__ int cnt[NBINS];
    __shared__ int wsum[8];
    __shared__ float4 sbox[CAP];
    __shared__ float  snarea[CAP];
    __shared__ int    sbs[5 * GB + 1];

    const int c    = blockIdx.x;
    const int tid  = threadIdx.x;
    const int lane = tid & 31, wid = tid >> 5;

    // ================= phase 1: prep (CTAs 0..16) =================
    if (c < T_RUNS + 1) {
        const bool is_box_block = (c < T_RUNS);
        cnt[tid] = 0;
        __syncthreads();

        float4 box[8];
        int    bin[8];
        if (is_box_block) {
            const float* src = dropout_preds + (size_t)c * M_BOX * 6;
            #pragma unroll
            for (int k = 0; k < M_BOX / 256; ++k) {
                const float* b6 = src + (tid + k * 256) * 6;
                box[k] = make_float4(b6[0], b6[1], b6[2], b6[3]);
                bin[k] = bin1d(box[k].y) * GB + bin1d(box[k].x);
                atomicAdd(&cnt[bin[k]], 1);
            }
        } else {
            #pragma unroll
            for (int k = 0; k < N_PRED / 256; ++k) {
                int p = tid + k * 256;
                const float* a = pred + p * 6;
                box[k] = make_float4(a[0], a[1], a[2], a[3]);
                bin[k] = bin1d(box[k].y) * GB + bin1d(box[k].x);
                atomicAdd(&cnt[bin[k]], 1);
                out[p] = 0.0f;        // out is poisoned; re-zero every run
            }
        }
        __syncthreads();

        // exclusive scan over 256 bins
        int v = cnt[tid];
        int inc = v;
        #pragma unroll
        for (int o = 1; o < 32; o <<= 1) {
            int nn = __shfl_up_sync(0xffffffffu, inc, o);
            if (lane >= o) inc += nn;
        }
        if (lane == 31) wsum[wid] = inc;
        __syncthreads();
        if (wid == 0) {
            int w = (lane < 8) ? wsum[lane] : 0;
            int wi = w;
            #pragma unroll
            for (int o = 1; o < 8; o <<= 1) {
                int nn = __shfl_up_sync(0xffffffffu, wi, o);
                if (lane >= o) wi += nn;
            }
            if (lane < 8) wsum[lane] = wi - w;
        }
        __syncthreads();
        const int start = inc - v + wsum[wid];
        cnt[tid] = start;
        __syncthreads();

        if (is_box_block) {
            g_bstart[c][tid] = start;
            if (tid == 0) g_bstart[c][NBINS] = M_BOX;
            #pragma unroll
            for (int k = 0; k < M_BOX / 256; ++k) {
                int pos = atomicAdd(&cnt[bin[k]], 1);
                g_sbox[c][pos] = box[k];
            }
        } else {
            g_pstart[tid] = start;
            if (tid == 0) g_pstart[NBINS] = N_PRED;
            #pragma unroll
            for (int k = 0; k < N_PRED / 256; ++k) {
                int pos = atomicAdd(&cnt[bin[k]], 1);
                g_pbox[pos] = box[k];
                g_perm[pos] = tid + k * 256;
            }
        }
        __syncthreads();
    }

    // ================= grid-wide sync (all 256 CTAs co-resident) =========
    if (tid == 0) {
        if (c < T_RUNS + 1) {
            __threadfence();
            atomicAdd((int*)&g_sync, 1);
        }
        while (g_sync < T_RUNS + 1) __nanosleep(64);
    }
    __syncthreads();
    __threadfence();                    // acquire prep writes

    // ================= phase 2: match (R4 body, 256-thread fill) ========
    const int yr = c & 15;
    const int t  = c >> 4;

    const int r0 = max(yr - 2, 0), r1 = min(yr + 2, GB - 1);
    const int bin_lo = r0 * GB, bin_hi = (r1 + 1) * GB;
    const int nbs = bin_hi - bin_lo + 1;      // <= 81

    const int base = g_bstart[t][bin_lo];
    const int endi = g_bstart[t][bin_hi];
    const int n    = endi - base;

    if (tid < nbs) sbs[tid] = g_bstart[t][bin_lo + tid];
    const int ncap = min(n, CAP);
    for (int i = tid; i < ncap; i += 256) {
        float4 b  = g_sbox[t][base + i];
        sbox[i]   = b;
        snarea[i] = -((b.z - b.x) * (b.w - b.y));
    }
    __syncthreads();

    const int ps = g_pstart[yr * GB], pe = g_pstart[(yr + 1) * GB];
    const bool all_smem = (n <= CAP);         // always true for uniform data

    for (int slot = ps + tid; slot < pe; slot += 256) {
        const float4 a  = g_pbox[slot];
        const float thr = (a.z - a.x) * (a.w - a.y) + EPS_F;

        const int xb0 = bin1d(a.x - WH_MAX), xb1 = bin1d(a.z);
        const int yb0 = max(bin1d(a.y - WH_MAX), r0);
        const int yb1 = min(bin1d(a.w), r1);

        float best = -1e30f;
        if (all_smem) {
            for (int yb = yb0; yb <= yb1; ++yb) {
                const int rb = yb * GB - bin_lo;
                const int s  = sbs[rb + xb0] - base;
                const int e  = sbs[rb + xb1 + 1] - base;
                #pragma unroll 4
                for (int m = s; m < e; ++m) {
                    float4 b  = sbox[m];
                    float ix1 = fmaxf(a.x, b.x);
                    float iy1 = fmaxf(a.y, b.y);
                    float ix2 = fminf(a.z, b.z);
                    float iy2 = fminf(a.w, b.w);
                    float dx  = fmaxf(ix2 - ix1, 0.0f);
                    float dy  = iy2 - iy1;        // dy<0 => inter<=0 < thr
                    best = fmaxf(best, fmaf(3.0f, dx * dy, snarea[m]));
                }
                if (best > thr) break;
            }
        } else {                                   // safety fallback (gmem)
            for (int yb = yb0; yb <= yb1; ++yb) {
                const int rb = yb * GB - bin_lo;
                const int s  = sbs[rb + xb0];
                const int e  = sbs[rb + xb1 + 1];
                for (int m = s; m < e; ++m) {
                    float4 b  = g_sbox[t][m];
                    float na  = -((b.z - b.x) * (b.w - b.y));
                    float ix1 = fmaxf(a.x, b.x);
                    float iy1 = fmaxf(a.y, b.y);
                    float ix2 = fminf(a.z, b.z);
                    float iy2 = fminf(a.w, b.w);
                    float dx  = fmaxf(ix2 - ix1, 0.0f);
                    float dy  = iy2 - iy1;
                    best = fmaxf(best, fmaf(3.0f, dx * dy, na));
                }
                if (best > thr) break;
            }
        }

        // 16 adds of exactly 1/16: order-independent & exact -> deterministic
        if (best > thr) atomicAdd(&out[g_perm[slot]], 1.0f / (float)T_RUNS);
    }

    // ================= epilogue: last CTA resets counters (replay-safe) ==
    __syncthreads();
    if (tid == 0) {
        __threadfence();
        int d = atomicAdd(&g_done, 1);
        if (d == NCTA - 1) {
            g_done = 0;
            g_sync = 0;
        }
    }
}

extern "C" void kernel_launch(void* const* d_in, const int* in_sizes, int n_in,
                              void* d_out, int out_size)
{
    const float* pred          = (const float*)d_in[0]; // [2048, 6]
    const float* dropout_preds = (const float*)d_in[1]; // [16, 2048, 6]
    // d_in[2] (dropout_cls_confs) unused by the reference computation.
    float* out = (float*)d_out;                          // [2048]

    fused_kernel<<<NCTA, 256>>>(pred, dropout_preds, out);
}

// round 10
// speedup vs baseline: 1.2220x; 1.1045x over previous
#include <cuda_runtime.h>
#include <cuda_bf16.h>

#define N_PRED 2048
#define T_RUNS 16
#define M_BOX  2048
#define EPS_F  1e-7f

#define GBY     16
#define GBX     32
#define NBINS   (GBY*GBX)       // 512
#define BIN_ORG (-28.0f)
#define INV_Y   (1.0f/42.0f)    // 16*42 = 672 covers [-28, 644)
#define INV_X   (1.0f/21.0f)    // 32*21 = 672
#define WH_MAX  55.0f           // box w,h in [5,55)
#define CAP     1280            // smem slab capacity
#define SBSW    36              // padded row width for sbs (<= 34 used)

// ---- device scratch (no allocations allowed) ----
__device__ float4 g_sbox[T_RUNS][M_BOX];      // binned boxes (x1,y1,x2,y2)
__device__ int    g_bstart[T_RUNS][NBINS+1];  // box bin prefix offsets per run
__device__ float4 g_pbox[N_PRED];             // pred boxes, bin-sorted
__device__ int    g_perm[N_PRED];             // sorted slot -> original pred idx
__device__ int    g_pstart[NBINS+1];          // pred bin prefix offsets

__device__ __forceinline__ int biny(float v) {
    int b = (int)floorf((v - BIN_ORG) * INV_Y);
    return min(max(b, 0), GBY - 1);
}
__device__ __forceinline__ int binx(float v) {
    int b = (int)floorf((v - BIN_ORG) * INV_X);
    return min(max(b, 0), GBX - 1);
}

// ---------------------------------------------------------------------------
// prep: blocks 0..15 counting-sort run t's boxes into 512 (y16 x x32) bins;
// block 16 sorts preds, writes g_pstart, zeroes out. 256 threads; the scan
// handles 2 bins per thread.
// ---------------------------------------------------------------------------
__global__ __launch_bounds__(256)
void prep_kernel(const float* __restrict__ pred,
                 const float* __restrict__ dropout_preds,
                 float* __restrict__ out)
{
    __shared__ int cnt[NBINS];
    __shared__ int wsum[8];
    const int tid  = threadIdx.x;
    const int lane = tid & 31, wid = tid >> 5;
    const bool is_box_block = (blockIdx.x < T_RUNS);

    cnt[tid] = 0;
    cnt[tid + 256] = 0;
    __syncthreads();

    // ---- count ----
    float4 box[8];
    int    bin[8];
    if (is_box_block) {
        const float* src = dropout_preds + (size_t)blockIdx.x * M_BOX * 6;
        #pragma unroll
        for (int k = 0; k < M_BOX / 256; ++k) {
            const float* b6 = src + (tid + k * 256) * 6;
            box[k] = make_float4(b6[0], b6[1], b6[2], b6[3]);
            bin[k] = biny(box[k].y) * GBX + binx(box[k].x);
            atomicAdd(&cnt[bin[k]], 1);
        }
    } else {
        #pragma unroll
        for (int k = 0; k < N_PRED / 256; ++k) {
            int p = tid + k * 256;
            const float* a = pred + p * 6;
            box[k] = make_float4(a[0], a[1], a[2], a[3]);
            bin[k] = biny(box[k].y) * GBX + binx(box[k].x);
            atomicAdd(&cnt[bin[k]], 1);
            out[p] = 0.0f;        // out is poisoned; zero before match
        }
    }
    __syncthreads();

    // ---- exclusive scan over 512 bins, 2 bins per thread ----
    const int v0 = cnt[2 * tid], v1 = cnt[2 * tid + 1];
    const int tv = v0 + v1;
    int inc = tv;
    #pragma unroll
    for (int o = 1; o < 32; o <<= 1) {
        int n = __shfl_up_sync(0xffffffffu, inc, o);
        if (lane >= o) inc += n;
    }
    if (lane == 31) wsum[wid] = inc;
    __syncthreads();
    if (wid == 0) {
        int w = (lane < 8) ? wsum[lane] : 0;
        int wi = w;
        #pragma unroll
        for (int o = 1; o < 8; o <<= 1) {
            int n = __shfl_up_sync(0xffffffffu, wi, o);
            if (lane >= o) wi += n;
        }
        if (lane < 8) wsum[lane] = wi - w;
    }
    __syncthreads();
    const int excl   = inc - tv + wsum[wid];
    const int start0 = excl;
    const int start1 = excl + v0;
    cnt[2 * tid]     = start0;               // running scatter offsets
    cnt[2 * tid + 1] = start1;
    __syncthreads();

    // ---- scatter ----
    if (is_box_block) {
        const int t = blockIdx.x;
        g_bstart[t][2 * tid]     = start0;
        g_bstart[t][2 * tid + 1] = start1;
        if (tid == 0) g_bstart[t][NBINS] = M_BOX;
        #pragma unroll
        for (int k = 0; k < M_BOX / 256; ++k) {
            int pos = atomicAdd(&cnt[bin[k]], 1);
            g_sbox[t][pos] = box[k];
        }
    } else {
        g_pstart[2 * tid]     = start0;
        g_pstart[2 * tid + 1] = start1;
        if (tid == 0) g_pstart[NBINS] = N_PRED;
        #pragma unroll
        for (int k = 0; k < N_PRED / 256; ++k) {
            int pos = atomicAdd(&cnt[bin[k]], 1);
            g_pbox[pos] = box[k];
            g_perm[pos] = tid + k * 256;
        }
    }
}

// ---------------------------------------------------------------------------
// match: CTA = (half, pred-y-row yr, run t), 128 threads, one thread per pred
// (R4's winning structure). New: the CTA reduces its preds' x-bin window and
// fills only the x-restricted sub-slab of rows [yr-2, yr+2] (~45% less fill);
// 32 x-bins cut scanned pairs ~17%. Outside-window boxes can't match.
// ---------------------------------------------------------------------------
__global__ __launch_bounds__(128)
void match_kernel(float* __restrict__ out)
{
    __shared__ float4 sbox[CAP];
    __shared__ float  snarea[CAP];
    __shared__ int    sbs[5 * SBSW];   // per-row prefix entries (global idx)
    __shared__ int    soff[6];         // smem row base offsets
    __shared__ int    sminb, smaxb;

    const int tid  = threadIdx.x;
    const int half = blockIdx.x;
    const int yr   = blockIdx.y;
    const int t    = blockIdx.z;

    const int r0 = max(yr - 2, 0), r1 = min(yr + 2, GBY - 1);
    const int nr = r1 - r0 + 1;

    const int ps  = g_pstart[yr * GBX], pe = g_pstart[(yr + 1) * GBX];
    const int mid = (ps + pe) >> 1;
    const int seg_s = half ? mid : ps;
    const int seg_e = half ? pe  : mid;

    if (tid == 0) { sminb = GBX; smaxb = -1; }
    __syncthreads();

    // ---- pass 1: CTA x-bin window over this CTA's preds ----
    for (int slot = seg_s + tid; slot < seg_e; slot += 128) {
        const float4 a = g_pbox[slot];
        atomicMin(&sminb, binx(a.x - WH_MAX));
        atomicMax(&smaxb, binx(a.z));
    }
    __syncthreads();
    const int cxb0 = sminb, cxb1 = smaxb;
    const bool any = (cxb1 >= cxb0);
    const int cw1 = any ? (cxb1 - cxb0 + 2) : 0;   // prefix entries per row

    // ---- load per-row prefix entries ----
    if (any) {
        for (int i = tid; i < nr * cw1; i += 128) {
            const int r = i / cw1, b = i - r * cw1;
            sbs[r * SBSW + b] = g_bstart[t][(r0 + r) * GBX + cxb0 + b];
        }
    }
    __syncthreads();
    if (any && tid == 0) {
        int o = 0;
        for (int r = 0; r < nr; ++r) {
            soff[r] = o;
            o += sbs[r * SBSW + cw1 - 1] - sbs[r * SBSW];
        }
        soff[nr] = o;
    }
    __syncthreads();
    const int total = any ? soff[nr] : 0;
    const bool all_smem = (total <= CAP);

    // ---- fill x-restricted sub-slab ----
    if (all_smem) {
        for (int i = tid; i < total; i += 128) {
            int r = 0;
            while (i >= soff[r + 1]) ++r;            // nr <= 5
            const int g = sbs[r * SBSW] + (i - soff[r]);
            const float4 b = g_sbox[t][g];
            sbox[i]   = b;
            snarea[i] = -((b.z - b.x) * (b.w - b.y));
        }
    }
    __syncthreads();

    // ---- scan: one thread per pred, exact per-pred windows ----
    for (int slot = seg_s + tid; slot < seg_e; slot += 128) {
        const float4 a  = g_pbox[slot];
        const float thr = (a.z - a.x) * (a.w - a.y) + EPS_F;

        const int xb0 = binx(a.x - WH_MAX), xb1 = binx(a.z);
        const int yb0 = max(biny(a.y - WH_MAX), r0);
        const int yb1 = min(biny(a.w), r1);

        float best = -1e30f;
        if (all_smem) {
            for (int yb = yb0; yb <= yb1; ++yb) {
                const int r    = yb - r0;
                const int rb   = r * SBSW - cxb0;
                const int adj  = soff[r] - sbs[r * SBSW];
                const int s    = sbs[rb + xb0] + adj;
                const int e    = sbs[rb + xb1 + 1] + adj;
                #pragma unroll 4
                for (int m = s; m < e; ++m) {
                    float4 b  = sbox[m];
                    float ix1 = fmaxf(a.x, b.x);
                    float iy1 = fmaxf(a.y, b.y);
                    float ix2 = fminf(a.z, b.z);
                    float iy2 = fminf(a.w, b.w);
                    float dx  = fmaxf(ix2 - ix1, 0.0f);
                    float dy  = iy2 - iy1;          // dy<0 => inter<=0 < thr
                    best = fmaxf(best, fmaf(3.0f, dx * dy, snarea[m]));
                }
                if (best > thr) break;
            }
        } else {                                     // safety fallback (gmem)
            for (int yb = yb0; yb <= yb1; ++yb) {
                const int rb = (yb - r0) * SBSW - cxb0;
                const int s  = sbs[rb + xb0];
                const int e  = sbs[rb + xb1 + 1];
                for (int m = s; m < e; ++m) {
                    float4 b  = g_sbox[t][m];
                    float na  = -((b.z - b.x) * (b.w - b.y));
                    float ix1 = fmaxf(a.x, b.x);
                    float iy1 = fmaxf(a.y, b.y);
                    float ix2 = fminf(a.z, b.z);
                    float iy2 = fminf(a.w, b.w);
                    float dx  = fmaxf(ix2 - ix1, 0.0f);
                    float dy  = iy2 - iy1;
                    best = fmaxf(best, fmaf(3.0f, dx * dy, na));
                }
                if (best > thr) break;
            }
        }

        // 16 adds of exactly 1/16: order-independent & exact -> deterministic
        if (best > thr) atomicAdd(&out[g_perm[slot]], 1.0f / (float)T_RUNS);
    }
}

extern "C" void kernel_launch(void* const* d_in, const int* in_sizes, int n_in,
                              void* d_out, int out_size)
{
    const float* pred          = (const float*)d_in[0]; // [2048, 6]
    const float* dropout_preds = (const float*)d_in[1]; // [16, 2048, 6]
    // d_in[2] (dropout_cls_confs) unused by the reference computation.
    float* out = (float*)d_out;                          // [2048]

    prep_kernel<<<T_RUNS + 1, 256>>>(pred, dropout_preds, out);
    match_kernel<<<dim3(2, GBY, T_RUNS), 128>>>(out);
}

// round 11
// speedup vs baseline: 1.2429x; 1.0171x over previous
#include <cuda_runtime.h>
#include <cuda_bf16.h>

#define N_PRED 2048
#define T_RUNS 16
#define M_BOX  2048
#define EPS_F  1e-7f

#define GBY     16
#define GBX     32
#define NBINS   (GBY*GBX)       // 512
#define BIN_ORG (-28.0f)
#define INV_Y   (1.0f/42.0f)    // 16*42 = 672 covers [-28, 644)
#define INV_X   (1.0f/21.0f)    // 32*21 = 672
#define WH_MAX  55.0f           // box w,h in [5,55)
#define CAP     1280            // smem slab capacity
#define SBSW    36              // padded row width for sbs (<= 34 used)

// ---- device scratch (no allocations allowed) ----
__device__ float4 g_sbox[T_RUNS][M_BOX];      // binned boxes (x1,y1,x2,y2)
__device__ int    g_bstart[T_RUNS][NBINS+1];  // box bin prefix offsets per run
__device__ float4 g_pbox[N_PRED];             // pred boxes, bin-sorted
__device__ int    g_perm[N_PRED];             // sorted slot -> original pred idx
__device__ int    g_pstart[NBINS+1];          // pred bin prefix offsets

__device__ __forceinline__ int biny(float v) {
    int b = (int)floorf((v - BIN_ORG) * INV_Y);
    return min(max(b, 0), GBY - 1);
}
__device__ __forceinline__ int binx(float v) {
    int b = (int)floorf((v - BIN_ORG) * INV_X);
    return min(max(b, 0), GBX - 1);
}

// ---------------------------------------------------------------------------
// prep: unchanged from R10 (512 y16 x x32 bins).
// ---------------------------------------------------------------------------
__global__ __launch_bounds__(256)
void prep_kernel(const float* __restrict__ pred,
                 const float* __restrict__ dropout_preds,
                 float* __restrict__ out)
{
    __shared__ int cnt[NBINS];
    __shared__ int wsum[8];
    const int tid  = threadIdx.x;
    const int lane = tid & 31, wid = tid >> 5;
    const bool is_box_block = (blockIdx.x < T_RUNS);

    cnt[tid] = 0;
    cnt[tid + 256] = 0;
    __syncthreads();

    float4 box[8];
    int    bin[8];
    if (is_box_block) {
        const float* src = dropout_preds + (size_t)blockIdx.x * M_BOX * 6;
        #pragma unroll
        for (int k = 0; k < M_BOX / 256; ++k) {
            const float* b6 = src + (tid + k * 256) * 6;
            box[k] = make_float4(b6[0], b6[1], b6[2], b6[3]);
            bin[k] = biny(box[k].y) * GBX + binx(box[k].x);
            atomicAdd(&cnt[bin[k]], 1);
        }
    } else {
        #pragma unroll
        for (int k = 0; k < N_PRED / 256; ++k) {
            int p = tid + k * 256;
            const float* a = pred + p * 6;
            box[k] = make_float4(a[0], a[1], a[2], a[3]);
            bin[k] = biny(box[k].y) * GBX + binx(box[k].x);
            atomicAdd(&cnt[bin[k]], 1);
            out[p] = 0.0f;        // out is poisoned; zero before match
        }
    }
    __syncthreads();

    const int v0 = cnt[2 * tid], v1 = cnt[2 * tid + 1];
    const int tv = v0 + v1;
    int inc = tv;
    #pragma unroll
    for (int o = 1; o < 32; o <<= 1) {
        int n = __shfl_up_sync(0xffffffffu, inc, o);
        if (lane >= o) inc += n;
    }
    if (lane == 31) wsum[wid] = inc;
    __syncthreads();
    if (wid == 0) {
        int w = (lane < 8) ? wsum[lane] : 0;
        int wi = w;
        #pragma unroll
        for (int o = 1; o < 8; o <<= 1) {
            int n = __shfl_up_sync(0xffffffffu, wi, o);
            if (lane >= o) wi += n;
        }
        if (lane < 8) wsum[lane] = wi - w;
    }
    __syncthreads();
    const int excl   = inc - tv + wsum[wid];
    const int start0 = excl;
    const int start1 = excl + v0;
    cnt[2 * tid]     = start0;
    cnt[2 * tid + 1] = start1;
    __syncthreads();

    if (is_box_block) {
        const int t = blockIdx.x;
        g_bstart[t][2 * tid]     = start0;
        g_bstart[t][2 * tid + 1] = start1;
        if (tid == 0) g_bstart[t][NBINS] = M_BOX;
        #pragma unroll
        for (int k = 0; k < M_BOX / 256; ++k) {
            int pos = atomicAdd(&cnt[bin[k]], 1);
            g_sbox[t][pos] = box[k];
        }
    } else {
        g_pstart[2 * tid]     = start0;
        g_pstart[2 * tid + 1] = start1;
        if (tid == 0) g_pstart[NBINS] = N_PRED;
        #pragma unroll
        for (int k = 0; k < N_PRED / 256; ++k) {
            int pos = atomicAdd(&cnt[bin[k]], 1);
            g_pbox[pos] = box[k];
            g_perm[pos] = tid + k * 256;
        }
    }
}

// ---------------------------------------------------------------------------
// match: CTA = (half, yr, t), 256 threads = 4 THREADS PER PRED (~64 preds).
// Warp-uniform y-row loop (5 rows); per-pred predicates gate the scan; after
// each row the 4-group max-combines via two full-mask shfl_xor at a uniform
// point and sets 'found' -> row-level early exit preserved, per-thread chain
// cut 4x, and 4096 warps (~7/SMSP) hide the LDS latency.
// ---------------------------------------------------------------------------
__global__ __launch_bounds__(256)
void match_kernel(float* __restrict__ out)
{
    __shared__ float4 sbox[CAP];
    __shared__ float  snarea[CAP];
    __shared__ int    sbs[5 * SBSW];   // per-row prefix entries (global idx)
    __shared__ int    soff[6];         // smem row base offsets
    __shared__ int    sminb, smaxb;

    const int tid  = threadIdx.x;
    const int half = blockIdx.x;
    const int yr   = blockIdx.y;
    const int t    = blockIdx.z;

    const int r0 = max(yr - 2, 0), r1 = min(yr + 2, GBY - 1);
    const int nr = r1 - r0 + 1;

    const int ps  = g_pstart[yr * GBX], pe = g_pstart[(yr + 1) * GBX];
    const int mid = (ps + pe) >> 1;
    const int seg_s = half ? mid : ps;
    const int seg_e = half ? pe  : mid;

    if (tid == 0) { sminb = GBX; smaxb = -1; }
    __syncthreads();

    // ---- CTA x-bin window over this CTA's preds ----
    for (int slot = seg_s + tid; slot < seg_e; slot += 256) {
        const float4 a = g_pbox[slot];
        atomicMin(&sminb, binx(a.x - WH_MAX));
        atomicMax(&smaxb, binx(a.z));
    }
    __syncthreads();
    const int cxb0 = sminb, cxb1 = smaxb;
    const bool anyp = (cxb1 >= cxb0);
    const int cw1 = anyp ? (cxb1 - cxb0 + 2) : 0;

    if (anyp) {
        for (int i = tid; i < nr * cw1; i += 256) {
            const int r = i / cw1, b = i - r * cw1;
            sbs[r * SBSW + b] = g_bstart[t][(r0 + r) * GBX + cxb0 + b];
        }
    }
    __syncthreads();
    if (anyp && tid == 0) {
        int o = 0;
        for (int r = 0; r < nr; ++r) {
            soff[r] = o;
            o += sbs[r * SBSW + cw1 - 1] - sbs[r * SBSW];
        }
        soff[nr] = o;
    }
    __syncthreads();
    const int total = anyp ? soff[nr] : 0;
    const bool all_smem = (total <= CAP);

    // ---- fill x-restricted sub-slab ----
    if (all_smem) {
        for (int i = tid; i < total; i += 256) {
            int r = 0;
            while (i >= soff[r + 1]) ++r;            // nr <= 5
            const int g = sbs[r * SBSW] + (i - soff[r]);
            const float4 b = g_sbox[t][g];
            sbox[i]   = b;
            snarea[i] = -((b.z - b.x) * (b.w - b.y));
        }
    }
    __syncthreads();

    // ---- scan: 4 threads per pred ----
    const int grp = tid >> 2, sub = tid & 3;

    for (int slot0 = seg_s; slot0 < seg_e; slot0 += 64) {   // CTA-uniform trips
        const int slot   = slot0 + grp;
        const bool valid = (slot < seg_e);

        float4 a = make_float4(0.f, 0.f, 0.f, 0.f);
        float thr = 0.0f;
        int xb0 = 0, xb1 = 0, yb0 = 0, yb1 = -1, p = 0;
        if (valid) {
            a   = g_pbox[slot];
            p   = g_perm[slot];
            thr = (a.z - a.x) * (a.w - a.y) + EPS_F;
            xb0 = binx(a.x - WH_MAX); xb1 = binx(a.z);
            yb0 = max(biny(a.y - WH_MAX), r0);
            yb1 = min(biny(a.w), r1);
        }

        bool found = false;
        #pragma unroll
        for (int r = 0; r < 5; ++r) {               // warp-uniform row loop
            const int yb = r0 + r;
            if (yb > r1) break;                     // CTA-uniform bound
            float acc = -1e30f;
            const bool doscan = valid && !found && yb >= yb0 && yb <= yb1;
            if (doscan) {
                if (all_smem) {
                    const int rb  = r * SBSW - cxb0;
                    const int adj = soff[r] - sbs[r * SBSW];
                    const int s   = sbs[rb + xb0] + adj;
                    const int e   = sbs[rb + xb1 + 1] + adj;
                    #pragma unroll 2
                    for (int m = s + sub; m < e; m += 4) {
                        float4 b  = sbox[m];
                        float ix1 = fmaxf(a.x, b.x);
                        float iy1 = fmaxf(a.y, b.y);
                        float ix2 = fminf(a.z, b.z);
                        float iy2 = fminf(a.w, b.w);
                        float dx  = fmaxf(ix2 - ix1, 0.0f);
                        float dy  = iy2 - iy1;      // dy<0 => inter<=0 < thr
                        acc = fmaxf(acc, fmaf(3.0f, dx * dy, snarea[m]));
                    }
                } else {                             // safety fallback (gmem)
                    const int rb = r * SBSW - cxb0;
                    const int s  = sbs[rb + xb0];
                    const int e  = sbs[rb + xb1 + 1];
                    for (int m = s + sub; m < e; m += 4) {
                        float4 b  = g_sbox[t][m];
                        float na  = -((b.z - b.x) * (b.w - b.y));
                        float ix1 = fmaxf(a.x, b.x);
                        float iy1 = fmaxf(a.y, b.y);
                        float ix2 = fminf(a.z, b.z);
                        float iy2 = fminf(a.w, b.w);
                        float dx  = fmaxf(ix2 - ix1, 0.0f);
                        float dy  = iy2 - iy1;
                        acc = fmaxf(acc, fmaf(3.0f, dx * dy, na));
                    }
                }
            }
            // warp-uniform point, full mask: combine the 4-group (exact max)
            acc = fmaxf(acc, __shfl_xor_sync(0xffffffffu, acc, 1));
            acc = fmaxf(acc, __shfl_xor_sync(0xffffffffu, acc, 2));
            found = found || (acc > thr);
        }

        // 16 adds of exactly 1/16: order-independent & exact -> deterministic
        if (valid && sub == 0 && found)
            atomicAdd(&out[p], 1.0f / (float)T_RUNS);
    }
}

extern "C" void kernel_launch(void* const* d_in, const int* in_sizes, int n_in,
                              void* d_out, int out_size)
{
    const float* pred          = (const float*)d_in[0]; // [2048, 6]
    const float* dropout_preds = (const float*)d_in[1]; // [16, 2048, 6]
    // d_in[2] (dropout_cls_confs) unused by the reference computation.
    float* out = (float*)d_out;                          // [2048]

    prep_kernel<<<T_RUNS + 1, 256>>>(pred, dropout_preds, out);
    match_kernel<<<dim3(2, GBY, T_RUNS), 256>>>(out);
}